// round 13
// baseline (speedup 1.0000x reference)
#include <cuda_runtime.h>
#include <cuda_bf16.h>
#include <cuda_fp16.h>
#include <math.h>
#include <stdint.h>

#define BDIM 2048
#define TDIM 128
#define FDIM 128
#define HDIM 512
#define LDIM 8
#define KWIN 10
#define GATES 2064
#define H6 85
#define NPAD 2176            // GATES padded to 17*128
#define KPAD 640             // 128 (x) + 512 (h); dt handled as rank-1 in epilogue
#define NCHUNK 5             // K-chunks of 128: chunk0 = x, chunks 1-4 = h
#define CONVK 5120           // HDIM * KWIN
#define CONVCHUNK 80         // CONVK / 64
#define MTILE 256
#define NTILE 128
#define CWSCALE 64.0f
#define CWINV  0.015625f
// step stage (K=128 chunk): A fp16 64K @0, B fp16 32K @65536
#define BUF_BYTES 98304
#define SMEM_BYTES (2 * BUF_BYTES)     // 192KB, 1 CTA/SM
// conv stage: A(lh) fp16 16K @0, Bhi 16K @16384, Blo 16K @32768
#define CBUF_BYTES 49152
#define CSMEM_BYTES (3 * CBUF_BYTES)

// ---------------- device globals (static; no runtime allocation) ---------------
__device__ __align__(256) __half g_W[(size_t)NPAD * KPAD];     // W^T fp16, (N,K)
__device__ __align__(256) __half g_xT[(size_t)TDIM * BDIM * FDIM]; // x (T,B,F) fp16
__device__ __align__(256) __half g_h[BDIM * HDIM];             // hidden state fp16
__device__ __align__(256) __half g_xo[(size_t)BDIM * NPAD];    // gate pre-acts fp16
__device__ __align__(256) __half g_hring[KWIN * BDIM * HDIM];  // last-K h, fp16
__device__ __align__(256) __half g_lh[(size_t)BDIM * CONVK];   // local_h fp16
__device__ __align__(256) __half g_cwhi[(size_t)HDIM * CONVK]; // 64*conv_w hi
__device__ __align__(256) __half g_cwlo[(size_t)HDIM * CONVK]; // 64*conv_w lo
__device__ __align__(256) float g_dt[TDIM * BDIM];    // time transposed (T,B) fp32
__device__ __align__(256) float g_Wdt[NPAD];          // dt row fp32
__device__ __align__(256) float g_bc[NPAD];
__device__ __align__(256) float g_c[BDIM * HDIM];
__device__ __align__(256) float g_ldis[BDIM * KWIN];
__device__ __align__(256) float g_mh[BDIM * HDIM];
__device__ __align__(256) float g_t1[BDIM * H6];
__device__ __align__(256) float g_theme[BDIM * HDIM];

__device__ __forceinline__ float fsig(float x) { return 1.0f / (1.0f + __expf(-x)); }
__device__ __forceinline__ float ftanh(float x) {
    return 1.0f - 2.0f / (__expf(2.0f * x) + 1.0f);
}

// ---------------- PTX helpers (compute_103-legal, sm_80-era) --------------------
__device__ __forceinline__ uint32_t smem_u32(const void* p) {
    uint32_t a;
    asm("{ .reg .u64 t; cvta.to.shared.u64 t, %1; cvt.u32.u64 %0, t; }" : "=r"(a) : "l"(p));
    return a;
}
__device__ __forceinline__ void cp16(uint32_t saddr, const void* g) {
    asm volatile("cp.async.cg.shared.global [%0], [%1], 16;" :: "r"(saddr), "l"(g)
                 : "memory");
}
#define CP_COMMIT() asm volatile("cp.async.commit_group;" ::: "memory")
#define CP_WAIT0()  asm volatile("cp.async.wait_group 0;" ::: "memory")
#define CP_WAIT1()  asm volatile("cp.async.wait_group 1;" ::: "memory")

__device__ __forceinline__ void ldsm_x4(uint32_t* r, uint32_t addr) {
    asm volatile("ldmatrix.sync.aligned.m8n8.x4.shared.b16 {%0,%1,%2,%3}, [%4];"
                 : "=r"(r[0]), "=r"(r[1]), "=r"(r[2]), "=r"(r[3]) : "r"(addr));
}
__device__ __forceinline__ void ldsm_x2(uint32_t* r, uint32_t addr) {
    asm volatile("ldmatrix.sync.aligned.m8n8.x2.shared.b16 {%0,%1}, [%2];"
                 : "=r"(r[0]), "=r"(r[1]) : "r"(addr));
}
__device__ __forceinline__ void mma_f16(float* d, const uint32_t* a, const uint32_t* b) {
    asm volatile(
        "mma.sync.aligned.m16n8k16.row.col.f32.f16.f16.f32 "
        "{%0,%1,%2,%3}, {%4,%5,%6,%7}, {%8,%9}, {%0,%1,%2,%3};"
        : "+f"(d[0]), "+f"(d[1]), "+f"(d[2]), "+f"(d[3])
        : "r"(a[0]), "r"(a[1]), "r"(a[2]), "r"(a[3]), "r"(b[0]), "r"(b[1]));
}

// ---------------- prep ----------------------------------------------------------
__global__ void prep_kernel(const float* __restrict__ x, const float* __restrict__ tmv,
                            const float* __restrict__ Wk, const float* __restrict__ bk,
                            const float* __restrict__ Wr, const float* __restrict__ br,
                            const float* __restrict__ conv_w) {
    size_t id = (size_t)blockIdx.x * blockDim.x + threadIdx.x;
    if (id < (size_t)NPAD * KPAD) {
        int n = (int)(id / KPAD), k = (int)(id % KPAD);
        float v = 0.0f;
        if (n < GATES)
            v = (k < FDIM) ? Wk[k * GATES + n] : Wr[(k - FDIM) * GATES + n];
        g_W[id] = __float2half_rn(v);
    }
    if (id < NPAD) {
        g_bc[id]  = (id < GATES) ? bk[id] + br[id] : 0.0f;
        g_Wdt[id] = (id < GATES) ? Wk[(size_t)FDIM * GATES + id] +
                                   Wr[(size_t)HDIM * GATES + id] : 0.0f;
    }
    if (id < (size_t)TDIM * BDIM * FDIM) {
        int f = (int)(id & (FDIM - 1));
        int b = (int)((id >> 7) & (BDIM - 1));
        int t = (int)(id >> 18);
        g_xT[id] = __float2half_rn(x[((size_t)b * TDIM + t) * FDIM + f]);
    }
    if (id < (size_t)TDIM * BDIM) {
        int b = (int)(id % BDIM), t = (int)(id / BDIM);
        g_dt[id] = tmv[(size_t)b * TDIM + t];
    }
    if (id < (size_t)BDIM * HDIM) {
        g_c[id] = 0.0f;
        g_h[id] = __float2half_rn(0.0f);
    }
    if (id < (size_t)HDIM * CONVK) {
        float v = conv_w[id] * CWSCALE;   // scale keeps lo out of fp16 subnormals
        __half hi = __float2half_rn(v);
        g_cwhi[id] = hi;
        g_cwlo[id] = __float2half_rn(v - __half2float(hi));
    }
}

// ---------------- step chunk loader (K=128 chunk; 256B rows, 16 segments) -------
// chunk 0 = x[t] (F=128), chunks 1-4 = h[:, (c-1)*128 : c*128]
__device__ __forceinline__ void step_load_chunk(uint32_t sb, int buf, int c, int t,
                                                int bm, int bn) {
    int tid = threadIdx.x;
    uint32_t base = sb + (uint32_t)buf * BUF_BYTES;
    // A: 256 rows x 128 fp16 = 4096 16B vectors
#pragma unroll
    for (int it = 0; it < 16; ++it) {
        int idx = tid + it * 256;
        int r = idx >> 4, s = idx & 15;
        uint32_t soff = (uint32_t)(r * 256 + ((s ^ (r & 7)) << 4));
        const __half* gp;
        if (c == 0)
            gp = g_xT + ((size_t)t * BDIM + bm + r) * FDIM + s * 8;
        else
            gp = g_h + (size_t)(bm + r) * HDIM + (c - 1) * 128 + s * 8;
        cp16(base + soff, gp);
    }
    // B: 128 rows x 128 fp16 = 2048 vectors
#pragma unroll
    for (int it = 0; it < 8; ++it) {
        int idx = tid + it * 256;
        int r = idx >> 4, s = idx & 15;
        uint32_t soff = (uint32_t)(r * 256 + ((s ^ (r & 7)) << 4));
        size_t go = (size_t)(bn + r) * KPAD + c * 128 + s * 8;
        cp16(base + 65536 + soff, g_W + go);
    }
}

// ---------------- compute one K=128 chunk, 64x64 warp tile (single pass) --------
__device__ __forceinline__ void step_compute_chunk(uint32_t base, int warp_m, int warp_n,
                                                   int lane, float (*acc)[8][4]) {
    uint32_t Ab = base, Bb = base + 65536;
    int arow_off = (lane & 7) + ((lane & 8) ? 8 : 0);
    int bL = lane & 15;
#pragma unroll
    for (int ks = 0; ks < 8; ++ks) {
        uint32_t ah[4][4];
        int aseg = 2 * ks + ((lane & 16) ? 1 : 0);
        int bseg = 2 * ks + ((bL & 8) ? 1 : 0);
#pragma unroll
        for (int mi = 0; mi < 4; ++mi) {
            int r = warp_m * 64 + mi * 16 + arow_off;
            uint32_t off = (uint32_t)(r * 256 + ((aseg ^ (r & 7)) << 4));
            ldsm_x4(ah[mi], Ab + off);
        }
#pragma unroll
        for (int ni = 0; ni < 8; ++ni) {
            uint32_t bb[2];
            int r = warp_n * 64 + ni * 8 + (bL & 7);
            uint32_t off = (uint32_t)(r * 256 + ((bseg ^ (r & 7)) << 4));
            ldsm_x2(bb, Bb + off);
#pragma unroll
            for (int mi = 0; mi < 4; ++mi) mma_f16(acc[mi][ni], ah[mi], bb);
        }
    }
}

// ---------------- per-step GEMM: xo = [x_t|h] @ W + dt*Wdt + bc (fp16 out) ------
__global__ void __launch_bounds__(256, 1) step_mma_kernel(int t) {
    extern __shared__ char smem[];
    uint32_t sb = smem_u32(smem);
    int tid = threadIdx.x, wid = tid >> 5, lane = tid & 31;
    int warp_m = wid >> 1, warp_n = wid & 1;
    int bn = blockIdx.x * NTILE, bm = blockIdx.y * MTILE;

    float acc[4][8][4];
#pragma unroll
    for (int i = 0; i < 4; ++i)
#pragma unroll
        for (int j = 0; j < 8; ++j)
#pragma unroll
            for (int k = 0; k < 4; ++k) acc[i][j][k] = 0.0f;

    step_load_chunk(sb, 0, 0, t, bm, bn);
    CP_COMMIT();
    for (int c = 0; c < NCHUNK; ++c) {
        CP_WAIT0();
        __syncthreads();
        if (c + 1 < NCHUNK) {
            step_load_chunk(sb, (c + 1) & 1, c + 1, t, bm, bn);
            CP_COMMIT();
        }
        step_compute_chunk(sb + (uint32_t)(c & 1) * BUF_BYTES, warp_m, warp_n, lane, acc);
    }

    // epilogue: acc + bias + dt*Wdt -> g_xo (fp16)
    int gr = lane >> 2, gc = (lane & 3) * 2;
#pragma unroll
    for (int mi = 0; mi < 4; ++mi) {
        int row0 = bm + warp_m * 64 + mi * 16 + gr;
        float dt0 = g_dt[t * BDIM + row0];
        float dt8 = g_dt[t * BDIM + row0 + 8];
#pragma unroll
        for (int ni = 0; ni < 8; ++ni) {
            int col = bn + warp_n * 64 + ni * 8 + gc;
            float b0 = g_bc[col], b1 = g_bc[col + 1];
            float w0 = g_Wdt[col], w1 = g_Wdt[col + 1];
            __half2 v0 = __floats2half2_rn(acc[mi][ni][0] + b0 + dt0 * w0,
                                           acc[mi][ni][1] + b1 + dt0 * w1);
            __half2 v1 = __floats2half2_rn(acc[mi][ni][2] + b0 + dt8 * w0,
                                           acc[mi][ni][3] + b1 + dt8 * w1);
            *(__half2*)&g_xo[(size_t)row0 * NPAD + col] = v0;
            *(__half2*)&g_xo[(size_t)(row0 + 8) * NPAD + col] = v1;
        }
    }
}

// ---------------- conv tail: A fp16 single + W fp16 hi/lo 2-pass ----------------
__device__ __forceinline__ void conv_load_chunk(uint32_t sb, int buf, int c,
                                                int bm, int bn) {
    int tid = threadIdx.x;
    uint32_t base = sb + (uint32_t)buf * CBUF_BYTES;
#pragma unroll
    for (int it = 0; it < 4; ++it) {
        int idx = tid + it * 256;
        int r = idx >> 3, s = idx & 7;
        uint32_t soff = (uint32_t)(r * 128 + ((s ^ (r & 7)) << 4));
        size_t go = (size_t)(bm + r) * CONVK + c * 64 + s * 8;
        cp16(base + soff, g_lh + go);
    }
#pragma unroll
    for (int it = 0; it < 4; ++it) {
        int idx = tid + it * 256;
        int r = idx >> 3, s = idx & 7;
        uint32_t soff = (uint32_t)(r * 128 + ((s ^ (r & 7)) << 4));
        size_t go = (size_t)(bn + r) * CONVK + c * 64 + s * 8;
        cp16(base + 16384 + soff, g_cwhi + go);
        cp16(base + 32768 + soff, g_cwlo + go);
    }
}

__device__ __forceinline__ void conv_compute_chunk(uint32_t base, int warp_m, int warp_n,
                                                   int lane, float (*acc)[4][4]) {
    uint32_t Ab = base, Bhi = base + 16384, Blo = base + 32768;
    int arow_off = (lane & 7) + ((lane & 8) ? 8 : 0);
    int bL = lane & 15;
#pragma unroll
    for (int ks = 0; ks < 4; ++ks) {
        uint32_t ah[4][4];
        int aseg = 2 * ks + ((lane & 16) ? 1 : 0);
        int bseg = 2 * ks + ((bL & 8) ? 1 : 0);
#pragma unroll
        for (int mi = 0; mi < 4; ++mi) {
            int r = warp_m * 64 + mi * 16 + arow_off;
            uint32_t off = (uint32_t)(r * 128 + ((aseg ^ (r & 7)) << 4));
            ldsm_x4(ah[mi], Ab + off);
        }
#pragma unroll
        for (int ni = 0; ni < 4; ++ni) {
            uint32_t bh[2], bl_[2];
            int r = warp_n * 32 + ni * 8 + (bL & 7);
            uint32_t off = (uint32_t)(r * 128 + ((bseg ^ (r & 7)) << 4));
            ldsm_x2(bh, Bhi + off);
            ldsm_x2(bl_, Blo + off);
#pragma unroll
            for (int mi = 0; mi < 4; ++mi) mma_f16(acc[mi][ni], ah[mi], bh);
#pragma unroll
            for (int mi = 0; mi < 4; ++mi) mma_f16(acc[mi][ni], ah[mi], bl_);
        }
    }
}

__global__ void __launch_bounds__(256, 1) conv_mma_kernel(const float* __restrict__ cb,
                                                          float* __restrict__ out) {
    extern __shared__ char smem[];
    uint32_t sb = smem_u32(smem);
    int tid = threadIdx.x, wid = tid >> 5, lane = tid & 31;
    int warp_m = wid >> 2, warp_n = wid & 3;
    int bn = blockIdx.x * 128, bm = blockIdx.y * 128;

    float acc[4][4][4];
#pragma unroll
    for (int i = 0; i < 4; ++i)
#pragma unroll
        for (int j = 0; j < 4; ++j)
#pragma unroll
            for (int k = 0; k < 4; ++k) acc[i][j][k] = 0.0f;

    conv_load_chunk(sb, 0, 0, bm, bn); CP_COMMIT();
    conv_load_chunk(sb, 1, 1, bm, bn); CP_COMMIT();
    for (int c = 0; c < CONVCHUNK; ++c) {
        if (c + 1 < CONVCHUNK) { CP_WAIT1(); } else { CP_WAIT0(); }
        __syncthreads();
        if (c + 2 < CONVCHUNK) {
            conv_load_chunk(sb, (c + 2) % 3, c + 2, bm, bn);
            CP_COMMIT();
        }
        conv_compute_chunk(sb + (uint32_t)(c % 3) * CBUF_BYTES, warp_m, warp_n, lane, acc);
    }

    int gr = lane >> 2, gc = (lane & 3) * 2;
#pragma unroll
    for (int mi = 0; mi < 4; ++mi) {
        int row0 = bm + warp_m * 64 + mi * 16 + gr;
#pragma unroll
        for (int ni = 0; ni < 4; ++ni) {
            int col = bn + warp_n * 32 + ni * 8 + gc;
            float b0 = cb[col], b1 = cb[col + 1];
            float2 v0, v1;
            v0.x = g_theme[(size_t)row0 * HDIM + col] * (acc[mi][ni][0] * CWINV + b0);
            v0.y = g_theme[(size_t)row0 * HDIM + col + 1] * (acc[mi][ni][1] * CWINV + b1);
            v1.x = g_theme[(size_t)(row0 + 8) * HDIM + col] * (acc[mi][ni][2] * CWINV + b0);
            v1.y = g_theme[(size_t)(row0 + 8) * HDIM + col + 1] * (acc[mi][ni][3] * CWINV + b1);
            *(float2*)&out[(size_t)row0 * HDIM + col] = v0;
            *(float2*)&out[(size_t)(row0 + 8) * HDIM + col] = v1;
        }
    }
}

// ---------------- per-step gating (fp16 xo in, fast-math transcendentals) -------
__global__ void gate_kernel(int t, float* __restrict__ dist_out) {
    int b = blockIdx.x;
    int tid = threadIdx.x;
    __shared__ float sfm[LDIM], sim[LDIM];
    const __half* xo = g_xo + (size_t)b * NPAD;

    if (tid == 0) {
        float z[LDIM], m = -1e30f;
#pragma unroll
        for (int l = 0; l < LDIM; l++) { z[l] = __half2float(xo[l]); m = fmaxf(m, z[l]); }
        float s = 0.0f;
#pragma unroll
        for (int l = 0; l < LDIM; l++) { z[l] = __expf(z[l] - m); s += z[l]; }
        float inv = 1.0f / s, cs = 0.0f, dsum = 0.0f;
#pragma unroll
        for (int l = 0; l < LDIM; l++) { cs += z[l] * inv; sfm[l] = cs; dsum += cs; }
        dist_out[b] = 1.0f - dsum * (1.0f / LDIM);
    }
    if (tid == 32) {
        float z[LDIM], m = -1e30f;
#pragma unroll
        for (int l = 0; l < LDIM; l++) { z[l] = __half2float(xo[LDIM + l]); m = fmaxf(m, z[l]); }
        float s = 0.0f;
#pragma unroll
        for (int l = 0; l < LDIM; l++) { z[l] = __expf(z[l] - m); s += z[l]; }
        float inv = 1.0f / s, cs = 0.0f;
#pragma unroll
        for (int l = LDIM - 1; l >= 0; l--) { cs += z[l] * inv; sim[l] = cs; }
    }
    __syncthreads();

    __half* hslot = g_hring + (size_t)(t % KWIN) * BDIM * HDIM;
    int base = b * HDIM;
    for (int idx = tid; idx < HDIM; idx += blockDim.x) {
        int l = idx >> 6;
        float f  = fsig(__half2float(xo[16 + idx]));
        float ii = fsig(__half2float(xo[16 + 512 + idx]));
        float oo = fsig(__half2float(xo[16 + 1024 + idx]));
        float ci = ftanh(__half2float(xo[16 + 1536 + idx]));
        float cl = g_c[base + idx];
        float fm = sfm[l], im = sim[l], ov = fm * im;
        float cn = ov * (f * cl + ii * ci) + (fm - ov) * cl + (im - ov) * ci;
        float hn = oo * ftanh(cn);
        g_c[base + idx] = cn;
        __half hh = __float2half_rn(hn);
        hslot[base + idx] = hh;
        g_h[base + idx] = hh;
    }
}

// ---------------- tail kernels ---------------------------------------------------
__global__ void ldis_kernel(const float* __restrict__ dist) {
    int b = blockIdx.x * blockDim.x + threadIdx.x;
    if (b >= BDIM) return;
    float v[KWIN], s = 0.0f;
#pragma unroll
    for (int k = 0; k < KWIN; k++) { s += dist[(size_t)(TDIM - KWIN + k) * BDIM + b]; v[k] = s; }
    float m = -1e30f;
#pragma unroll
    for (int k = 0; k < KWIN; k++) m = fmaxf(m, v[k]);
    float es = 0.0f;
#pragma unroll
    for (int k = 0; k < KWIN; k++) { v[k] = expf(v[k] - m); es += v[k]; }
    float inv = 1.0f / es;
#pragma unroll
    for (int k = 0; k < KWIN; k++) g_ldis[b * KWIN + k] = v[k] * inv;
}

// local_h (fp16, layout (B, h*KWIN+k)) + mean over k -> g_mh
__global__ void meanlh_kernel() {
    int id = blockIdx.x * blockDim.x + threadIdx.x;
    if (id >= BDIM * HDIM) return;
    int b = id >> 9;
    int hh = id & 511;
    float acc = 0.0f;
    size_t lbase = (size_t)b * CONVK + hh * KWIN;
#pragma unroll
    for (int k = 0; k < KWIN; k++) {
        int slot = (TDIM - KWIN + k) % KWIN;
        float hv = __half2float(g_hring[(size_t)slot * BDIM * HDIM + id]);
        float lv = hv * g_ldis[b * KWIN + k];
        g_lh[lbase + k] = __float2half_rn(lv);
        acc += lv;
    }
    g_mh[id] = acc * (1.0f / KWIN);
}

template <int EPI>
__global__ void __launch_bounds__(256) sgemm_kernel(
    const float* __restrict__ A, const float* __restrict__ W,
    const float* __restrict__ bias, float* __restrict__ out, int M, int N, int K)
{
    __shared__ float As[8][128];
    __shared__ float Bs[8][128];
    int tid = threadIdx.x;
    int bm = blockIdx.y * 128;
    int bn = blockIdx.x * 128;
    int ty = tid >> 4, tx = tid & 15;

    float acc[8][8];
#pragma unroll
    for (int i = 0; i < 8; i++)
#pragma unroll
        for (int j = 0; j < 8; j++) acc[i][j] = 0.0f;

    int aRow = tid >> 1, aK = (tid & 1) * 4;
    int bRow = tid >> 5, bCol = (tid & 31) * 4;

    for (int k0 = 0; k0 < K; k0 += 8) {
        int gm = bm + aRow;
#pragma unroll
        for (int j = 0; j < 4; j++) {
            int gk = k0 + aK + j;
            As[aK + j][aRow] = (gm < M && gk < K) ? A[(size_t)gm * K + gk] : 0.0f;
        }
        {
            int gk = k0 + bRow;
#pragma unroll
            for (int j = 0; j < 4; j++) {
                int gn = bn + bCol + j;
                Bs[bRow][bCol + j] = (gk < K && gn < N) ? W[(size_t)gk * N + gn] : 0.0f;
            }
        }
        __syncthreads();
#pragma unroll
        for (int kk = 0; kk < 8; kk++) {
            float a[8], bb[8];
#pragma unroll
            for (int i = 0; i < 8; i++) a[i] = As[kk][ty * 8 + i];
#pragma unroll
            for (int i = 0; i < 8; i++) bb[i] = Bs[kk][tx * 8 + i];
#pragma unroll
            for (int i = 0; i < 8; i++)
#pragma unroll
                for (int j = 0; j < 8; j++) acc[i][j] += a[i] * bb[j];
        }
        __syncthreads();
    }
#pragma unroll
    for (int i = 0; i < 8; i++) {
        int gm = bm + ty * 8 + i;
        if (gm >= M) continue;
#pragma unroll
        for (int j = 0; j < 8; j++) {
            int gn = bn + tx * 8 + j;
            if (gn >= N) continue;
            float v = acc[i][j] + bias[gn];
            if (EPI == 1) v = fmaxf(v, 0.0f);
            if (EPI == 2) v = 1.0f / (1.0f + expf(-v));
            out[(size_t)gm * N + gn] = v;
        }
    }
}

// ---------------- host launcher --------------------------------------------------
extern "C" void kernel_launch(void* const* d_in, const int* in_sizes, int n_in,
                              void* d_out, int out_size) {
    const float* x      = (const float*)d_in[0];
    const float* tmv    = (const float*)d_in[1];
    const float* Wk     = (const float*)d_in[2];
    const float* bk     = (const float*)d_in[3];
    const float* Wr     = (const float*)d_in[4];
    const float* br     = (const float*)d_in[5];
    const float* Ws     = (const float*)d_in[6];
    const float* bs     = (const float*)d_in[7];
    const float* Wrs    = (const float*)d_in[8];
    const float* brs    = (const float*)d_in[9];
    const float* conv_w = (const float*)d_in[10];
    const float* conv_b = (const float*)d_in[11];
    float* out = (float*)d_out;
    float* dist_out = out + (size_t)BDIM * HDIM;   // distance region: (T, B)

    float *p_mh, *p_t1, *p_theme;
    cudaGetSymbolAddress((void**)&p_mh, g_mh);
    cudaGetSymbolAddress((void**)&p_t1, g_t1);
    cudaGetSymbolAddress((void**)&p_theme, g_theme);

    cudaFuncSetAttribute(step_mma_kernel, cudaFuncAttributeMaxDynamicSharedMemorySize,
                         SMEM_BYTES);
    cudaFuncSetAttribute(conv_mma_kernel, cudaFuncAttributeMaxDynamicSharedMemorySize,
                         CSMEM_BYTES);

    // prep (largest id space: T*B*F = 33.5M)
    size_t prep_total = (size_t)TDIM * BDIM * FDIM;
    prep_kernel<<<(unsigned)((prep_total + 255) / 256), 256>>>(x, tmv, Wk, bk, Wr, br,
                                                               conv_w);

    // recurrent scan
    dim3 gstep(NPAD / NTILE, BDIM / MTILE);   // (17, 8)
    for (int t = 0; t < TDIM; t++) {
        step_mma_kernel<<<gstep, 256, SMEM_BYTES>>>(t);
        gate_kernel<<<BDIM, 256>>>(t, dist_out + (size_t)t * BDIM);
    }

    // tail
    ldis_kernel<<<(BDIM + 255) / 256, 256>>>(dist_out);
    meanlh_kernel<<<(BDIM * HDIM) / 256, 256>>>();
    sgemm_kernel<1><<<dim3(1, 16), 256>>>(p_mh, Ws, bs, p_t1, BDIM, H6, HDIM);
    sgemm_kernel<2><<<dim3(4, 16), 256>>>(p_t1, Wrs, brs, p_theme, BDIM, HDIM, H6);
    conv_mma_kernel<<<dim3(HDIM / 128, BDIM / 128), 256, CSMEM_BYTES>>>(conv_b, out);
}

// round 14
// speedup vs baseline: 1.0280x; 1.0280x over previous
#include <cuda_runtime.h>
#include <cuda_bf16.h>
#include <cuda_fp16.h>
#include <math.h>
#include <stdint.h>

#define BDIM 2048
#define TDIM 128
#define FDIM 128
#define HDIM 512
#define LDIM 8
#define KWIN 10
#define GATES 2064
#define H6 85
#define NPAD 2176            // GATES padded to 17*128
#define KPAD 640             // 128 (x) + 512 (h); dt handled as rank-1 in epilogue
#define NCHUNK 5             // K-chunks of 128: chunk0 = x, chunks 1-4 = h
#define CONVK 5120           // HDIM * KWIN
#define CONVCHUNK 80         // CONVK / 64
#define MTILE 256
#define NTILE 128
#define CWSCALE 64.0f
#define CWINV  0.015625f
// step stage (K=128 chunk): A fp16 64K @0, B fp16 32K @65536
#define BUF_BYTES 98304
#define SMEM_BYTES (2 * BUF_BYTES)     // 192KB, 1 CTA/SM
// conv stage: A(lh) fp16 16K @0, Bhi 16K @16384, Blo 16K @32768
#define CBUF_BYTES 49152
#define CSMEM_BYTES (3 * CBUF_BYTES)

// ---------------- device globals (static; no runtime allocation) ---------------
__device__ __align__(256) __half g_W[(size_t)NPAD * KPAD];     // W^T fp16, (N,K)
__device__ __align__(256) __half g_xT[(size_t)TDIM * BDIM * FDIM]; // x (T,B,F) fp16
__device__ __align__(256) __half g_h[BDIM * HDIM];             // hidden state fp16
__device__ __align__(256) __half g_hring[KWIN * BDIM * HDIM];  // last-K h, fp16
__device__ __align__(256) __half g_lh[(size_t)BDIM * CONVK];   // local_h fp16
__device__ __align__(256) __half g_cwhi[(size_t)HDIM * CONVK]; // 64*conv_w hi
__device__ __align__(256) __half g_cwlo[(size_t)HDIM * CONVK]; // 64*conv_w lo
__device__ __align__(256) float g_xo[(size_t)BDIM * NPAD];     // gate pre-acts fp32
__device__ __align__(256) float g_dt[TDIM * BDIM];    // time transposed (T,B) fp32
__device__ __align__(256) float g_Wdt[NPAD];          // dt row fp32
__device__ __align__(256) float g_bc[NPAD];
__device__ __align__(256) float g_c[BDIM * HDIM];
__device__ __align__(256) float g_ldis[BDIM * KWIN];
__device__ __align__(256) float g_mh[BDIM * HDIM];
__device__ __align__(256) float g_t1[BDIM * H6];
__device__ __align__(256) float g_theme[BDIM * HDIM];

__device__ __forceinline__ float fsig(float x) { return 1.0f / (1.0f + __expf(-x)); }
__device__ __forceinline__ float ftanh(float x) {
    return 1.0f - 2.0f / (__expf(2.0f * x) + 1.0f);
}

// ---------------- PTX helpers (compute_103-legal, sm_80-era) --------------------
__device__ __forceinline__ uint32_t smem_u32(const void* p) {
    uint32_t a;
    asm("{ .reg .u64 t; cvta.to.shared.u64 t, %1; cvt.u32.u64 %0, t; }" : "=r"(a) : "l"(p));
    return a;
}
__device__ __forceinline__ void cp16(uint32_t saddr, const void* g) {
    asm volatile("cp.async.cg.shared.global [%0], [%1], 16;" :: "r"(saddr), "l"(g)
                 : "memory");
}
#define CP_COMMIT() asm volatile("cp.async.commit_group;" ::: "memory")
#define CP_WAIT0()  asm volatile("cp.async.wait_group 0;" ::: "memory")
#define CP_WAIT1()  asm volatile("cp.async.wait_group 1;" ::: "memory")

__device__ __forceinline__ void ldsm_x4(uint32_t* r, uint32_t addr) {
    asm volatile("ldmatrix.sync.aligned.m8n8.x4.shared.b16 {%0,%1,%2,%3}, [%4];"
                 : "=r"(r[0]), "=r"(r[1]), "=r"(r[2]), "=r"(r[3]) : "r"(addr));
}
__device__ __forceinline__ void ldsm_x2(uint32_t* r, uint32_t addr) {
    asm volatile("ldmatrix.sync.aligned.m8n8.x2.shared.b16 {%0,%1}, [%2];"
                 : "=r"(r[0]), "=r"(r[1]) : "r"(addr));
}
__device__ __forceinline__ void mma_f16(float* d, const uint32_t* a, const uint32_t* b) {
    asm volatile(
        "mma.sync.aligned.m16n8k16.row.col.f32.f16.f16.f32 "
        "{%0,%1,%2,%3}, {%4,%5,%6,%7}, {%8,%9}, {%0,%1,%2,%3};"
        : "+f"(d[0]), "+f"(d[1]), "+f"(d[2]), "+f"(d[3])
        : "r"(a[0]), "r"(a[1]), "r"(a[2]), "r"(a[3]), "r"(b[0]), "r"(b[1]));
}

// ---------------- prep ----------------------------------------------------------
__global__ void prep_kernel(const float* __restrict__ x, const float* __restrict__ tmv,
                            const float* __restrict__ Wk, const float* __restrict__ bk,
                            const float* __restrict__ Wr, const float* __restrict__ br,
                            const float* __restrict__ conv_w) {
    size_t id = (size_t)blockIdx.x * blockDim.x + threadIdx.x;
    if (id < (size_t)NPAD * KPAD) {
        int n = (int)(id / KPAD), k = (int)(id % KPAD);
        float v = 0.0f;
        if (n < GATES)
            v = (k < FDIM) ? Wk[k * GATES + n] : Wr[(k - FDIM) * GATES + n];
        g_W[id] = __float2half_rn(v);
    }
    if (id < NPAD) {
        g_bc[id]  = (id < GATES) ? bk[id] + br[id] : 0.0f;
        g_Wdt[id] = (id < GATES) ? Wk[(size_t)FDIM * GATES + id] +
                                   Wr[(size_t)HDIM * GATES + id] : 0.0f;
    }
    if (id < (size_t)TDIM * BDIM * FDIM) {
        int f = (int)(id & (FDIM - 1));
        int b = (int)((id >> 7) & (BDIM - 1));
        int t = (int)(id >> 18);
        g_xT[id] = __float2half_rn(x[((size_t)b * TDIM + t) * FDIM + f]);
    }
    if (id < (size_t)TDIM * BDIM) {
        int b = (int)(id % BDIM), t = (int)(id / BDIM);
        g_dt[id] = tmv[(size_t)b * TDIM + t];
    }
    if (id < (size_t)BDIM * HDIM) {
        g_c[id] = 0.0f;
        g_h[id] = __float2half_rn(0.0f);
    }
    if (id < (size_t)HDIM * CONVK) {
        float v = conv_w[id] * CWSCALE;   // scale keeps lo out of fp16 subnormals
        __half hi = __float2half_rn(v);
        g_cwhi[id] = hi;
        g_cwlo[id] = __float2half_rn(v - __half2float(hi));
    }
}

// ---------------- step chunk loader (K=128 chunk; 256B rows, 16 segments) -------
// chunk 0 = x[t] (F=128), chunks 1-4 = h[:, (c-1)*128 : c*128]
__device__ __forceinline__ void step_load_chunk(uint32_t sb, int buf, int c, int t,
                                                int bm, int bn) {
    int tid = threadIdx.x;
    uint32_t base = sb + (uint32_t)buf * BUF_BYTES;
    // A: 256 rows x 128 fp16 = 4096 16B vectors
#pragma unroll
    for (int it = 0; it < 16; ++it) {
        int idx = tid + it * 256;
        int r = idx >> 4, s = idx & 15;
        uint32_t soff = (uint32_t)(r * 256 + ((s ^ (r & 7)) << 4));
        const __half* gp;
        if (c == 0)
            gp = g_xT + ((size_t)t * BDIM + bm + r) * FDIM + s * 8;
        else
            gp = g_h + (size_t)(bm + r) * HDIM + (c - 1) * 128 + s * 8;
        cp16(base + soff, gp);
    }
    // B: 128 rows x 128 fp16 = 2048 vectors
#pragma unroll
    for (int it = 0; it < 8; ++it) {
        int idx = tid + it * 256;
        int r = idx >> 4, s = idx & 15;
        uint32_t soff = (uint32_t)(r * 256 + ((s ^ (r & 7)) << 4));
        size_t go = (size_t)(bn + r) * KPAD + c * 128 + s * 8;
        cp16(base + 65536 + soff, g_W + go);
    }
}

// ---------------- compute one K=128 chunk, 64x64 warp tile (single pass) --------
// 8 warps = 4 (m) x 2 (n). B loaded 2 ni-tiles per ldmatrix.x4:
// lanes 0-7 -> (ni, khalf0)=b0, 8-15 -> (ni, khalf1)=b1,
// lanes 16-23 -> (ni+1, khalf0), 24-31 -> (ni+1, khalf1).
__device__ __forceinline__ void step_compute_chunk(uint32_t base, int warp_m, int warp_n,
                                                   int lane, float (*acc)[8][4]) {
    uint32_t Ab = base, Bb = base + 65536;
    int arow_off = (lane & 7) + ((lane & 8) ? 8 : 0);
    int bsel_ni = (lane >> 4) & 1;          // which of the pair this lane addresses
    int bsel_kh = (lane >> 3) & 1;          // k-half select
    int brow_in = lane & 7;
#pragma unroll
    for (int ks = 0; ks < 8; ++ks) {
        uint32_t ah[4][4];
        int aseg = 2 * ks + ((lane & 16) ? 1 : 0);
#pragma unroll
        for (int mi = 0; mi < 4; ++mi) {
            int r = warp_m * 64 + mi * 16 + arow_off;
            uint32_t off = (uint32_t)(r * 256 + ((aseg ^ (r & 7)) << 4));
            ldsm_x4(ah[mi], Ab + off);
        }
#pragma unroll
        for (int np = 0; np < 4; ++np) {
            uint32_t bb4[4];
            int r = warp_n * 64 + (np * 2 + bsel_ni) * 8 + brow_in;
            int seg = 2 * ks + bsel_kh;
            uint32_t off = (uint32_t)(r * 256 + ((seg ^ (r & 7)) << 4));
            ldsm_x4(bb4, Bb + off);
#pragma unroll
            for (int mi = 0; mi < 4; ++mi) mma_f16(acc[mi][np * 2], ah[mi], bb4);
#pragma unroll
            for (int mi = 0; mi < 4; ++mi) mma_f16(acc[mi][np * 2 + 1], ah[mi], bb4 + 2);
        }
    }
}

// ---------------- per-step GEMM: xo = [x_t|h] @ W + dt*Wdt + bc -----------------
__global__ void __launch_bounds__(256, 1) step_mma_kernel(int t) {
    extern __shared__ char smem[];
    uint32_t sb = smem_u32(smem);
    int tid = threadIdx.x, wid = tid >> 5, lane = tid & 31;
    int warp_m = wid >> 1, warp_n = wid & 1;
    int bn = blockIdx.x * NTILE, bm = blockIdx.y * MTILE;

    float acc[4][8][4];
#pragma unroll
    for (int i = 0; i < 4; ++i)
#pragma unroll
        for (int j = 0; j < 8; ++j)
#pragma unroll
            for (int k = 0; k < 4; ++k) acc[i][j][k] = 0.0f;

    step_load_chunk(sb, 0, 0, t, bm, bn);
    CP_COMMIT();
    for (int c = 0; c < NCHUNK; ++c) {
        CP_WAIT0();
        __syncthreads();
        if (c + 1 < NCHUNK) {
            step_load_chunk(sb, (c + 1) & 1, c + 1, t, bm, bn);
            CP_COMMIT();
        }
        step_compute_chunk(sb + (uint32_t)(c & 1) * BUF_BYTES, warp_m, warp_n, lane, acc);
    }

    // epilogue: acc + bias + dt*Wdt -> g_xo (fp32)
    int gr = lane >> 2, gc = (lane & 3) * 2;
#pragma unroll
    for (int mi = 0; mi < 4; ++mi) {
        int row0 = bm + warp_m * 64 + mi * 16 + gr;
        float dt0 = g_dt[t * BDIM + row0];
        float dt8 = g_dt[t * BDIM + row0 + 8];
#pragma unroll
        for (int ni = 0; ni < 8; ++ni) {
            int col = bn + warp_n * 64 + ni * 8 + gc;
            float b0 = g_bc[col], b1 = g_bc[col + 1];
            float w0 = g_Wdt[col], w1 = g_Wdt[col + 1];
            float2 v0 = make_float2(acc[mi][ni][0] + b0 + dt0 * w0,
                                    acc[mi][ni][1] + b1 + dt0 * w1);
            float2 v1 = make_float2(acc[mi][ni][2] + b0 + dt8 * w0,
                                    acc[mi][ni][3] + b1 + dt8 * w1);
            *(float2*)&g_xo[(size_t)row0 * NPAD + col] = v0;
            *(float2*)&g_xo[(size_t)(row0 + 8) * NPAD + col] = v1;
        }
    }
}

// ---------------- conv tail: A fp16 single + W fp16 hi/lo 2-pass ----------------
__device__ __forceinline__ void conv_load_chunk(uint32_t sb, int buf, int c,
                                                int bm, int bn) {
    int tid = threadIdx.x;
    uint32_t base = sb + (uint32_t)buf * CBUF_BYTES;
#pragma unroll
    for (int it = 0; it < 4; ++it) {
        int idx = tid + it * 256;
        int r = idx >> 3, s = idx & 7;
        uint32_t soff = (uint32_t)(r * 128 + ((s ^ (r & 7)) << 4));
        size_t go = (size_t)(bm + r) * CONVK + c * 64 + s * 8;
        cp16(base + soff, g_lh + go);
    }
#pragma unroll
    for (int it = 0; it < 4; ++it) {
        int idx = tid + it * 256;
        int r = idx >> 3, s = idx & 7;
        uint32_t soff = (uint32_t)(r * 128 + ((s ^ (r & 7)) << 4));
        size_t go = (size_t)(bn + r) * CONVK + c * 64 + s * 8;
        cp16(base + 16384 + soff, g_cwhi + go);
        cp16(base + 32768 + soff, g_cwlo + go);
    }
}

__device__ __forceinline__ void conv_compute_chunk(uint32_t base, int warp_m, int warp_n,
                                                   int lane, float (*acc)[4][4]) {
    uint32_t Ab = base, Bhi = base + 16384, Blo = base + 32768;
    int arow_off = (lane & 7) + ((lane & 8) ? 8 : 0);
    int bL = lane & 15;
#pragma unroll
    for (int ks = 0; ks < 4; ++ks) {
        uint32_t ah[4][4];
        int aseg = 2 * ks + ((lane & 16) ? 1 : 0);
        int bseg = 2 * ks + ((bL & 8) ? 1 : 0);
#pragma unroll
        for (int mi = 0; mi < 4; ++mi) {
            int r = warp_m * 64 + mi * 16 + arow_off;
            uint32_t off = (uint32_t)(r * 128 + ((aseg ^ (r & 7)) << 4));
            ldsm_x4(ah[mi], Ab + off);
        }
#pragma unroll
        for (int ni = 0; ni < 4; ++ni) {
            uint32_t bh[2], bl_[2];
            int r = warp_n * 32 + ni * 8 + (bL & 7);
            uint32_t off = (uint32_t)(r * 128 + ((bseg ^ (r & 7)) << 4));
            ldsm_x2(bh, Bhi + off);
            ldsm_x2(bl_, Blo + off);
#pragma unroll
            for (int mi = 0; mi < 4; ++mi) mma_f16(acc[mi][ni], ah[mi], bh);
#pragma unroll
            for (int mi = 0; mi < 4; ++mi) mma_f16(acc[mi][ni], ah[mi], bl_);
        }
    }
}

__global__ void __launch_bounds__(256, 1) conv_mma_kernel(const float* __restrict__ cb,
                                                          float* __restrict__ out) {
    extern __shared__ char smem[];
    uint32_t sb = smem_u32(smem);
    int tid = threadIdx.x, wid = tid >> 5, lane = tid & 31;
    int warp_m = wid >> 2, warp_n = wid & 3;
    int bn = blockIdx.x * 128, bm = blockIdx.y * 128;

    float acc[4][4][4];
#pragma unroll
    for (int i = 0; i < 4; ++i)
#pragma unroll
        for (int j = 0; j < 4; ++j)
#pragma unroll
            for (int k = 0; k < 4; ++k) acc[i][j][k] = 0.0f;

    conv_load_chunk(sb, 0, 0, bm, bn); CP_COMMIT();
    conv_load_chunk(sb, 1, 1, bm, bn); CP_COMMIT();
    for (int c = 0; c < CONVCHUNK; ++c) {
        if (c + 1 < CONVCHUNK) { CP_WAIT1(); } else { CP_WAIT0(); }
        __syncthreads();
        if (c + 2 < CONVCHUNK) {
            conv_load_chunk(sb, (c + 2) % 3, c + 2, bm, bn);
            CP_COMMIT();
        }
        conv_compute_chunk(sb + (uint32_t)(c % 3) * CBUF_BYTES, warp_m, warp_n, lane, acc);
    }

    int gr = lane >> 2, gc = (lane & 3) * 2;
#pragma unroll
    for (int mi = 0; mi < 4; ++mi) {
        int row0 = bm + warp_m * 64 + mi * 16 + gr;
#pragma unroll
        for (int ni = 0; ni < 4; ++ni) {
            int col = bn + warp_n * 32 + ni * 8 + gc;
            float b0 = cb[col], b1 = cb[col + 1];
            float2 v0, v1;
            v0.x = g_theme[(size_t)row0 * HDIM + col] * (acc[mi][ni][0] * CWINV + b0);
            v0.y = g_theme[(size_t)row0 * HDIM + col + 1] * (acc[mi][ni][1] * CWINV + b1);
            v1.x = g_theme[(size_t)(row0 + 8) * HDIM + col] * (acc[mi][ni][2] * CWINV + b0);
            v1.y = g_theme[(size_t)(row0 + 8) * HDIM + col + 1] * (acc[mi][ni][3] * CWINV + b1);
            *(float2*)&out[(size_t)row0 * HDIM + col] = v0;
            *(float2*)&out[(size_t)(row0 + 8) * HDIM + col] = v1;
        }
    }
}

// ---------------- per-step gating (fp32 xo in, fast-math transcendentals) -------
__global__ void gate_kernel(int t, float* __restrict__ dist_out) {
    int b = blockIdx.x;
    int tid = threadIdx.x;
    __shared__ float sfm[LDIM], sim[LDIM];
    const float* xo = g_xo + (size_t)b * NPAD;

    if (tid == 0) {
        float z[LDIM], m = -1e30f;
#pragma unroll
        for (int l = 0; l < LDIM; l++) { z[l] = xo[l]; m = fmaxf(m, z[l]); }
        float s = 0.0f;
#pragma unroll
        for (int l = 0; l < LDIM; l++) { z[l] = __expf(z[l] - m); s += z[l]; }
        float inv = 1.0f / s, cs = 0.0f, dsum = 0.0f;
#pragma unroll
        for (int l = 0; l < LDIM; l++) { cs += z[l] * inv; sfm[l] = cs; dsum += cs; }
        dist_out[b] = 1.0f - dsum * (1.0f / LDIM);
    }
    if (tid == 32) {
        float z[LDIM], m = -1e30f;
#pragma unroll
        for (int l = 0; l < LDIM; l++) { z[l] = xo[LDIM + l]; m = fmaxf(m, z[l]); }
        float s = 0.0f;
#pragma unroll
        for (int l = 0; l < LDIM; l++) { z[l] = __expf(z[l] - m); s += z[l]; }
        float inv = 1.0f / s, cs = 0.0f;
#pragma unroll
        for (int l = LDIM - 1; l >= 0; l--) { cs += z[l] * inv; sim[l] = cs; }
    }
    __syncthreads();

    __half* hslot = g_hring + (size_t)(t % KWIN) * BDIM * HDIM;
    int base = b * HDIM;
    for (int idx = tid; idx < HDIM; idx += blockDim.x) {
        int l = idx >> 6;
        float f  = fsig(xo[16 + idx]);
        float ii = fsig(xo[16 + 512 + idx]);
        float oo = fsig(xo[16 + 1024 + idx]);
        float ci = ftanh(xo[16 + 1536 + idx]);
        float cl = g_c[base + idx];
        float fm = sfm[l], im = sim[l], ov = fm * im;
        float cn = ov * (f * cl + ii * ci) + (fm - ov) * cl + (im - ov) * ci;
        float hn = oo * ftanh(cn);
        g_c[base + idx] = cn;
        __half hh = __float2half_rn(hn);
        hslot[base + idx] = hh;
        g_h[base + idx] = hh;
    }
}

// ---------------- tail kernels ---------------------------------------------------
__global__ void ldis_kernel(const float* __restrict__ dist) {
    int b = blockIdx.x * blockDim.x + threadIdx.x;
    if (b >= BDIM) return;
    float v[KWIN], s = 0.0f;
#pragma unroll
    for (int k = 0; k < KWIN; k++) { s += dist[(size_t)(TDIM - KWIN + k) * BDIM + b]; v[k] = s; }
    float m = -1e30f;
#pragma unroll
    for (int k = 0; k < KWIN; k++) m = fmaxf(m, v[k]);
    float es = 0.0f;
#pragma unroll
    for (int k = 0; k < KWIN; k++) { v[k] = expf(v[k] - m); es += v[k]; }
    float inv = 1.0f / es;
#pragma unroll
    for (int k = 0; k < KWIN; k++) g_ldis[b * KWIN + k] = v[k] * inv;
}

// local_h (fp16, layout (B, h*KWIN+k)) + mean over k -> g_mh
__global__ void meanlh_kernel() {
    int id = blockIdx.x * blockDim.x + threadIdx.x;
    if (id >= BDIM * HDIM) return;
    int b = id >> 9;
    int hh = id & 511;
    float acc = 0.0f;
    size_t lbase = (size_t)b * CONVK + hh * KWIN;
#pragma unroll
    for (int k = 0; k < KWIN; k++) {
        int slot = (TDIM - KWIN + k) % KWIN;
        float hv = __half2float(g_hring[(size_t)slot * BDIM * HDIM + id]);
        float lv = hv * g_ldis[b * KWIN + k];
        g_lh[lbase + k] = __float2half_rn(lv);
        acc += lv;
    }
    g_mh[id] = acc * (1.0f / KWIN);
}

template <int EPI>
__global__ void __launch_bounds__(256) sgemm_kernel(
    const float* __restrict__ A, const float* __restrict__ W,
    const float* __restrict__ bias, float* __restrict__ out, int M, int N, int K)
{
    __shared__ float As[8][128];
    __shared__ float Bs[8][128];
    int tid = threadIdx.x;
    int bm = blockIdx.y * 128;
    int bn = blockIdx.x * 128;
    int ty = tid >> 4, tx = tid & 15;

    float acc[8][8];
#pragma unroll
    for (int i = 0; i < 8; i++)
#pragma unroll
        for (int j = 0; j < 8; j++) acc[i][j] = 0.0f;

    int aRow = tid >> 1, aK = (tid & 1) * 4;
    int bRow = tid >> 5, bCol = (tid & 31) * 4;

    for (int k0 = 0; k0 < K; k0 += 8) {
        int gm = bm + aRow;
#pragma unroll
        for (int j = 0; j < 4; j++) {
            int gk = k0 + aK + j;
            As[aK + j][aRow] = (gm < M && gk < K) ? A[(size_t)gm * K + gk] : 0.0f;
        }
        {
            int gk = k0 + bRow;
#pragma unroll
            for (int j = 0; j < 4; j++) {
                int gn = bn + bCol + j;
                Bs[bRow][bCol + j] = (gk < K && gn < N) ? W[(size_t)gk * N + gn] : 0.0f;
            }
        }
        __syncthreads();
#pragma unroll
        for (int kk = 0; kk < 8; kk++) {
            float a[8], bb[8];
#pragma unroll
            for (int i = 0; i < 8; i++) a[i] = As[kk][ty * 8 + i];
#pragma unroll
            for (int i = 0; i < 8; i++) bb[i] = Bs[kk][tx * 8 + i];
#pragma unroll
            for (int i = 0; i < 8; i++)
#pragma unroll
                for (int j = 0; j < 8; j++) acc[i][j] += a[i] * bb[j];
        }
        __syncthreads();
    }
#pragma unroll
    for (int i = 0; i < 8; i++) {
        int gm = bm + ty * 8 + i;
        if (gm >= M) continue;
#pragma unroll
        for (int j = 0; j < 8; j++) {
            int gn = bn + tx * 8 + j;
            if (gn >= N) continue;
            float v = acc[i][j] + bias[gn];
            if (EPI == 1) v = fmaxf(v, 0.0f);
            if (EPI == 2) v = 1.0f / (1.0f + expf(-v));
            out[(size_t)gm * N + gn] = v;
        }
    }
}

// ---------------- host launcher --------------------------------------------------
extern "C" void kernel_launch(void* const* d_in, const int* in_sizes, int n_in,
                              void* d_out, int out_size) {
    const float* x      = (const float*)d_in[0];
    const float* tmv    = (const float*)d_in[1];
    const float* Wk     = (const float*)d_in[2];
    const float* bk     = (const float*)d_in[3];
    const float* Wr     = (const float*)d_in[4];
    const float* br     = (const float*)d_in[5];
    const float* Ws     = (const float*)d_in[6];
    const float* bs     = (const float*)d_in[7];
    const float* Wrs    = (const float*)d_in[8];
    const float* brs    = (const float*)d_in[9];
    const float* conv_w = (const float*)d_in[10];
    const float* conv_b = (const float*)d_in[11];
    float* out = (float*)d_out;
    float* dist_out = out + (size_t)BDIM * HDIM;   // distance region: (T, B)

    float *p_mh, *p_t1, *p_theme;
    cudaGetSymbolAddress((void**)&p_mh, g_mh);
    cudaGetSymbolAddress((void**)&p_t1, g_t1);
    cudaGetSymbolAddress((void**)&p_theme, g_theme);

    cudaFuncSetAttribute(step_mma_kernel, cudaFuncAttributeMaxDynamicSharedMemorySize,
                         SMEM_BYTES);
    cudaFuncSetAttribute(conv_mma_kernel, cudaFuncAttributeMaxDynamicSharedMemorySize,
                         CSMEM_BYTES);

    // prep (largest id space: T*B*F = 33.5M)
    size_t prep_total = (size_t)TDIM * BDIM * FDIM;
    prep_kernel<<<(unsigned)((prep_total + 255) / 256), 256>>>(x, tmv, Wk, bk, Wr, br,
                                                               conv_w);

    // recurrent scan
    dim3 gstep(NPAD / NTILE, BDIM / MTILE);   // (17, 8)
    for (int t = 0; t < TDIM; t++) {
        step_mma_kernel<<<gstep, 256, SMEM_BYTES>>>(t);
        gate_kernel<<<BDIM, 256>>>(t, dist_out + (size_t)t * BDIM);
    }

    // tail
    ldis_kernel<<<(BDIM + 255) / 256, 256>>>(dist_out);
    meanlh_kernel<<<(BDIM * HDIM) / 256, 256>>>();
    sgemm_kernel<1><<<dim3(1, 16), 256>>>(p_mh, Ws, bs, p_t1, BDIM, H6, HDIM);
    sgemm_kernel<2><<<dim3(4, 16), 256>>>(p_t1, Wrs, brs, p_theme, BDIM, HDIM, H6);
    conv_mma_kernel<<<dim3(HDIM / 128, BDIM / 128), 256, CSMEM_BYTES>>>(conv_b, out);
}

// round 15
// speedup vs baseline: 1.1642x; 1.1326x over previous
#include <cuda_runtime.h>
#include <cuda_bf16.h>
#include <cuda_fp16.h>
#include <math.h>
#include <stdint.h>

#define BDIM 2048
#define TDIM 128
#define FDIM 128
#define HDIM 512
#define LDIM 8
#define KWIN 10
#define GATES 2064
#define H6 85
#define NPAD 2176            // GATES padded to 17*128
#define KPAD 640             // 128 (x) + 512 (h); dt handled as rank-1 in epilogue
#define NCHUNK 5             // K-chunks of 128: chunk0 = x, chunks 1-4 = h
#define CONVK 5120           // HDIM * KWIN
#define CONVCHUNK 80         // CONVK / 64
#define MTILE 256
#define NTILE 128
#define CWSCALE 64.0f
#define CWINV  0.015625f
// step stage (K=128 chunk): A fp16 64K, B fp16 32K, stages at smem+1024
#define BUF_BYTES 98304
#define SMEM_BYTES (1024 + 2 * BUF_BYTES)
// swizzled global blocks (in halfs)
#define ABLK_H 32768         // 64KB A tile block
#define BBLK_H 16384         // 32KB B tile block
// conv stage: A(lh) fp16 16K @0, Bhi 16K @16384, Blo 16K @32768
#define CBUF_BYTES 49152
#define CSMEM_BYTES (3 * CBUF_BYTES)

// ---------------- device globals (static; no runtime allocation) ---------------
__device__ __align__(256) __half g_Wsw[(size_t)17 * NCHUNK * BBLK_H];  // W swizzled
__device__ __align__(256) __half g_xsw[(size_t)TDIM * 8 * ABLK_H];     // x swizzled
__device__ __align__(256) __half g_hsw[(size_t)8 * 4 * ABLK_H];        // h swizzled
__device__ __align__(256) __half g_hring[KWIN * BDIM * HDIM];  // last-K h, fp16
__device__ __align__(256) __half g_lh[(size_t)BDIM * CONVK];   // local_h fp16
__device__ __align__(256) __half g_cwhi[(size_t)HDIM * CONVK]; // 64*conv_w hi
__device__ __align__(256) __half g_cwlo[(size_t)HDIM * CONVK]; // 64*conv_w lo
__device__ __align__(256) float g_xo[(size_t)BDIM * NPAD];     // gate pre-acts fp32
__device__ __align__(256) float g_dt[TDIM * BDIM];    // time transposed (T,B) fp32
__device__ __align__(256) float g_Wdt[NPAD];          // dt row fp32
__device__ __align__(256) float g_bc[NPAD];
__device__ __align__(256) float g_c[BDIM * HDIM];
__device__ __align__(256) float g_ldis[BDIM * KWIN];
__device__ __align__(256) float g_mh[BDIM * HDIM];
__device__ __align__(256) float g_t1[BDIM * H6];
__device__ __align__(256) float g_theme[BDIM * HDIM];

__device__ __forceinline__ float fsig(float x) { return 1.0f / (1.0f + __expf(-x)); }
__device__ __forceinline__ float ftanh(float x) {
    return 1.0f - 2.0f / (__expf(2.0f * x) + 1.0f);
}

// ---------------- PTX helpers (all <= sm_90 base features) ----------------------
__device__ __forceinline__ uint32_t smem_u32(const void* p) {
    uint32_t a;
    asm("{ .reg .u64 t; cvta.to.shared.u64 t, %1; cvt.u32.u64 %0, t; }" : "=r"(a) : "l"(p));
    return a;
}
__device__ __forceinline__ void cp16(uint32_t saddr, const void* g) {
    asm volatile("cp.async.cg.shared.global [%0], [%1], 16;" :: "r"(saddr), "l"(g)
                 : "memory");
}
#define CP_COMMIT() asm volatile("cp.async.commit_group;" ::: "memory")
#define CP_WAIT0()  asm volatile("cp.async.wait_group 0;" ::: "memory")
#define CP_WAIT1()  asm volatile("cp.async.wait_group 1;" ::: "memory")

// bulk async copy: one instruction per tile (UBLKCP), completes via mbarrier tx
__device__ __forceinline__ void cp_bulk(uint32_t dst, const void* src, uint32_t bytes,
                                        uint32_t mbar) {
    asm volatile(
        "cp.async.bulk.shared::cluster.global.mbarrier::complete_tx::bytes "
        "[%0], [%1], %2, [%3];"
        :: "r"(dst), "l"(src), "r"(bytes), "r"(mbar) : "memory");
}
#define MB_INIT(m, c) asm volatile("mbarrier.init.shared.b64 [%0], %1;" \
    :: "r"(m), "r"((uint32_t)(c)) : "memory")
#define MB_EXPECT(m, b) asm volatile( \
    "mbarrier.arrive.expect_tx.shared.b64 _, [%0], %1;" \
    :: "r"(m), "r"((uint32_t)(b)) : "memory")
#define FENCE_ASYNC() asm volatile("fence.proxy.async.shared::cta;" ::: "memory")
#define MB_WAIT(m, par) do { \
    uint32_t _m = (m), _p = (par), _d; \
    asm volatile("{\n\t.reg .pred p;\n\t" \
        "mbarrier.try_wait.parity.acquire.cta.shared::cta.b64 p, [%1], %2;\n\t" \
        "selp.b32 %0, 1, 0, p;\n\t}" : "=r"(_d) : "r"(_m), "r"(_p) : "memory"); \
    if (!_d) { \
        asm volatile("{\n\t.reg .pred P1;\n\tWL_%=:\n\t" \
            "mbarrier.try_wait.parity.acquire.cta.shared::cta.b64 P1, [%0], %1, 0x989680;\n\t" \
            "@P1 bra.uni WD_%=;\n\tbra.uni WL_%=;\n\tWD_%=:\n\t}" \
            :: "r"(_m), "r"(_p) : "memory"); \
    } } while (0)

__device__ __forceinline__ void ldsm_x4(uint32_t* r, uint32_t addr) {
    asm volatile("ldmatrix.sync.aligned.m8n8.x4.shared.b16 {%0,%1,%2,%3}, [%4];"
                 : "=r"(r[0]), "=r"(r[1]), "=r"(r[2]), "=r"(r[3]) : "r"(addr));
}
__device__ __forceinline__ void ldsm_x2(uint32_t* r, uint32_t addr) {
    asm volatile("ldmatrix.sync.aligned.m8n8.x2.shared.b16 {%0,%1}, [%2];"
                 : "=r"(r[0]), "=r"(r[1]) : "r"(addr));
}
__device__ __forceinline__ void mma_f16(float* d, const uint32_t* a, const uint32_t* b) {
    asm volatile(
        "mma.sync.aligned.m16n8k16.row.col.f32.f16.f16.f32 "
        "{%0,%1,%2,%3}, {%4,%5,%6,%7}, {%8,%9}, {%0,%1,%2,%3};"
        : "+f"(d[0]), "+f"(d[1]), "+f"(d[2]), "+f"(d[3])
        : "r"(a[0]), "r"(a[1]), "r"(a[2]), "r"(a[3]), "r"(b[0]), "r"(b[1]));
}

// ---------------- prep ----------------------------------------------------------
__global__ void prep_kernel(const float* __restrict__ x, const float* __restrict__ tmv,
                            const float* __restrict__ Wk, const float* __restrict__ bk,
                            const float* __restrict__ Wr, const float* __restrict__ br,
                            const float* __restrict__ conv_w) {
    size_t id = (size_t)blockIdx.x * blockDim.x + threadIdx.x;
    // W^T swizzled blocks: (n, k) -> block (n>>7)*5 + (k>>7)
    if (id < (size_t)NPAD * KPAD) {
        int n = (int)(id / KPAD), k = (int)(id % KPAD);
        float v = 0.0f;
        if (n < GATES)
            v = (k < FDIM) ? Wk[k * GATES + n] : Wr[(k - FDIM) * GATES + n];
        int r = n & 127, s = (k >> 3) & 15, e = k & 7;
        size_t off = (size_t)((n >> 7) * NCHUNK + (k >> 7)) * BBLK_H
                     + r * 128 + ((s ^ (r & 7)) << 3) + e;
        g_Wsw[off] = __float2half_rn(v);
    }
    if (id < NPAD) {
        g_bc[id]  = (id < GATES) ? bk[id] + br[id] : 0.0f;
        g_Wdt[id] = (id < GATES) ? Wk[(size_t)FDIM * GATES + id] +
                                   Wr[(size_t)HDIM * GATES + id] : 0.0f;
    }
    // x swizzled blocks: (t, b, f) -> block t*8 + (b>>8)
    if (id < (size_t)TDIM * BDIM * FDIM) {
        int f = (int)(id & (FDIM - 1));
        int b = (int)((id >> 7) & (BDIM - 1));
        int t = (int)(id >> 18);
        int r = b & 255, s = f >> 3, e = f & 7;
        size_t off = (size_t)(t * 8 + (b >> 8)) * ABLK_H
                     + r * 128 + ((s ^ (r & 7)) << 3) + e;
        g_xsw[off] = __float2half_rn(x[((size_t)b * TDIM + t) * FDIM + f]);
    }
    if (id < (size_t)TDIM * BDIM) {
        int b = (int)(id % BDIM), t = (int)(id / BDIM);
        g_dt[id] = tmv[(size_t)b * TDIM + t];
    }
    if (id < (size_t)BDIM * HDIM) {
        g_c[id] = 0.0f;
        g_hsw[id] = __float2half_rn(0.0f);   // 8*4*ABLK_H == BDIM*HDIM
    }
    if (id < (size_t)HDIM * CONVK) {
        float v = conv_w[id] * CWSCALE;
        __half hi = __float2half_rn(v);
        g_cwhi[id] = hi;
        g_cwlo[id] = __float2half_rn(v - __half2float(hi));
    }
}

// ---------------- compute one K=128 chunk, 64x64 warp tile (single pass) --------
__device__ __forceinline__ void step_compute_chunk(uint32_t base, int warp_m, int warp_n,
                                                   int lane, float (*acc)[8][4]) {
    uint32_t Ab = base, Bb = base + 65536;
    int arow_off = (lane & 7) + ((lane & 8) ? 8 : 0);
    int bsel_ni = (lane >> 4) & 1;
    int bsel_kh = (lane >> 3) & 1;
    int brow_in = lane & 7;
#pragma unroll
    for (int ks = 0; ks < 8; ++ks) {
        uint32_t ah[4][4];
        int aseg = 2 * ks + ((lane & 16) ? 1 : 0);
#pragma unroll
        for (int mi = 0; mi < 4; ++mi) {
            int r = warp_m * 64 + mi * 16 + arow_off;
            uint32_t off = (uint32_t)(r * 256 + ((aseg ^ (r & 7)) << 4));
            ldsm_x4(ah[mi], Ab + off);
        }
#pragma unroll
        for (int np = 0; np < 4; ++np) {
            uint32_t bb4[4];
            int r = warp_n * 64 + (np * 2 + bsel_ni) * 8 + brow_in;
            int seg = 2 * ks + bsel_kh;
            uint32_t off = (uint32_t)(r * 256 + ((seg ^ (r & 7)) << 4));
            ldsm_x4(bb4, Bb + off);
#pragma unroll
            for (int mi = 0; mi < 4; ++mi) mma_f16(acc[mi][np * 2], ah[mi], bb4);
#pragma unroll
            for (int mi = 0; mi < 4; ++mi) mma_f16(acc[mi][np * 2 + 1], ah[mi], bb4 + 2);
        }
    }
}

// ---------------- per-step GEMM: bulk-copy loads + HMMA --------------------------
__global__ void __launch_bounds__(256, 1) step_mma_kernel(int t) {
    extern __shared__ char smem[];
    uint32_t sb = smem_u32(smem);
    int tid = threadIdx.x, wid = tid >> 5, lane = tid & 31;
    int warp_m = wid >> 1, warp_n = wid & 1;
    int bn_tile = blockIdx.x, bm_tile = blockIdx.y;
    int bn = bn_tile * NTILE, bm = bm_tile * MTILE;

    // mbarriers at smem+0 / smem+8; stages at smem+1024
    if (tid == 0) { MB_INIT(sb, 1); MB_INIT(sb + 8, 1); }
    __syncthreads();
    if (tid == 0) {
        FENCE_ASYNC();
        MB_EXPECT(sb, BUF_BYTES);
        cp_bulk(sb + 1024, g_xsw + (size_t)(t * 8 + bm_tile) * ABLK_H, 65536, sb);
        cp_bulk(sb + 1024 + 65536, g_Wsw + (size_t)(bn_tile * NCHUNK) * BBLK_H, 32768, sb);
    }

    float acc[4][8][4];
#pragma unroll
    for (int i = 0; i < 4; ++i)
#pragma unroll
        for (int j = 0; j < 8; ++j)
#pragma unroll
            for (int k = 0; k < 4; ++k) acc[i][j][k] = 0.0f;

    for (int c = 0; c < NCHUNK; ++c) {
        int st = c & 1;
        MB_WAIT(sb + 8 * st, (uint32_t)((c >> 1) & 1));
        __syncthreads();   // all warps done computing chunk c-1 (buffer (c+1)&1)
        if (c + 1 < NCHUNK && tid == 0) {
            int st2 = (c + 1) & 1;
            uint32_t dst = sb + 1024 + (uint32_t)st2 * BUF_BYTES;
            MB_EXPECT(sb + 8 * st2, BUF_BYTES);
            // chunk c+1 >= 1 -> A comes from h
            cp_bulk(dst, g_hsw + (size_t)(bm_tile * 4 + c) * ABLK_H, 65536, sb + 8 * st2);
            cp_bulk(dst + 65536, g_Wsw + (size_t)(bn_tile * NCHUNK + c + 1) * BBLK_H,
                    32768, sb + 8 * st2);
        }
        step_compute_chunk(sb + 1024 + (uint32_t)st * BUF_BYTES, warp_m, warp_n, lane, acc);
    }

    // epilogue: acc + bias + dt*Wdt -> g_xo (fp32)
    int gr = lane >> 2, gc = (lane & 3) * 2;
#pragma unroll
    for (int mi = 0; mi < 4; ++mi) {
        int row0 = bm + warp_m * 64 + mi * 16 + gr;
        float dt0 = g_dt[t * BDIM + row0];
        float dt8 = g_dt[t * BDIM + row0 + 8];
#pragma unroll
        for (int ni = 0; ni < 8; ++ni) {
            int col = bn + warp_n * 64 + ni * 8 + gc;
            float b0 = g_bc[col], b1 = g_bc[col + 1];
            float w0 = g_Wdt[col], w1 = g_Wdt[col + 1];
            float2 v0 = make_float2(acc[mi][ni][0] + b0 + dt0 * w0,
                                    acc[mi][ni][1] + b1 + dt0 * w1);
            float2 v1 = make_float2(acc[mi][ni][2] + b0 + dt8 * w0,
                                    acc[mi][ni][3] + b1 + dt8 * w1);
            *(float2*)&g_xo[(size_t)row0 * NPAD + col] = v0;
            *(float2*)&g_xo[(size_t)(row0 + 8) * NPAD + col] = v1;
        }
    }
}

// ---------------- conv tail: A fp16 single + W fp16 hi/lo 2-pass ----------------
__device__ __forceinline__ void conv_load_chunk(uint32_t sb, int buf, int c,
                                                int bm, int bn) {
    int tid = threadIdx.x;
    uint32_t base = sb + (uint32_t)buf * CBUF_BYTES;
#pragma unroll
    for (int it = 0; it < 4; ++it) {
        int idx = tid + it * 256;
        int r = idx >> 3, s = idx & 7;
        uint32_t soff = (uint32_t)(r * 128 + ((s ^ (r & 7)) << 4));
        size_t go = (size_t)(bm + r) * CONVK + c * 64 + s * 8;
        cp16(base + soff, g_lh + go);
    }
#pragma unroll
    for (int it = 0; it < 4; ++it) {
        int idx = tid + it * 256;
        int r = idx >> 3, s = idx & 7;
        uint32_t soff = (uint32_t)(r * 128 + ((s ^ (r & 7)) << 4));
        size_t go = (size_t)(bn + r) * CONVK + c * 64 + s * 8;
        cp16(base + 16384 + soff, g_cwhi + go);
        cp16(base + 32768 + soff, g_cwlo + go);
    }
}

__device__ __forceinline__ void conv_compute_chunk(uint32_t base, int warp_m, int warp_n,
                                                   int lane, float (*acc)[4][4]) {
    uint32_t Ab = base, Bhi = base + 16384, Blo = base + 32768;
    int arow_off = (lane & 7) + ((lane & 8) ? 8 : 0);
    int bL = lane & 15;
#pragma unroll
    for (int ks = 0; ks < 4; ++ks) {
        uint32_t ah[4][4];
        int aseg = 2 * ks + ((lane & 16) ? 1 : 0);
        int bseg = 2 * ks + ((bL & 8) ? 1 : 0);
#pragma unroll
        for (int mi = 0; mi < 4; ++mi) {
            int r = warp_m * 64 + mi * 16 + arow_off;
            uint32_t off = (uint32_t)(r * 128 + ((aseg ^ (r & 7)) << 4));
            ldsm_x4(ah[mi], Ab + off);
        }
#pragma unroll
        for (int ni = 0; ni < 4; ++ni) {
            uint32_t bh[2], bl_[2];
            int r = warp_n * 32 + ni * 8 + (bL & 7);
            uint32_t off = (uint32_t)(r * 128 + ((bseg ^ (r & 7)) << 4));
            ldsm_x2(bh, Bhi + off);
            ldsm_x2(bl_, Blo + off);
#pragma unroll
            for (int mi = 0; mi < 4; ++mi) mma_f16(acc[mi][ni], ah[mi], bh);
#pragma unroll
            for (int mi = 0; mi < 4; ++mi) mma_f16(acc[mi][ni], ah[mi], bl_);
        }
    }
}

__global__ void __launch_bounds__(256, 1) conv_mma_kernel(const float* __restrict__ cb,
                                                          float* __restrict__ out) {
    extern __shared__ char smem[];
    uint32_t sb = smem_u32(smem);
    int tid = threadIdx.x, wid = tid >> 5, lane = tid & 31;
    int warp_m = wid >> 2, warp_n = wid & 3;
    int bn = blockIdx.x * 128, bm = blockIdx.y * 128;

    float acc[4][4][4];
#pragma unroll
    for (int i = 0; i < 4; ++i)
#pragma unroll
        for (int j = 0; j < 4; ++j)
#pragma unroll
            for (int k = 0; k < 4; ++k) acc[i][j][k] = 0.0f;

    conv_load_chunk(sb, 0, 0, bm, bn); CP_COMMIT();
    conv_load_chunk(sb, 1, 1, bm, bn); CP_COMMIT();
    for (int c = 0; c < CONVCHUNK; ++c) {
        if (c + 1 < CONVCHUNK) { CP_WAIT1(); } else { CP_WAIT0(); }
        __syncthreads();
        if (c + 2 < CONVCHUNK) {
            conv_load_chunk(sb, (c + 2) % 3, c + 2, bm, bn);
            CP_COMMIT();
        }
        conv_compute_chunk(sb + (uint32_t)(c % 3) * CBUF_BYTES, warp_m, warp_n, lane, acc);
    }

    int gr = lane >> 2, gc = (lane & 3) * 2;
#pragma unroll
    for (int mi = 0; mi < 4; ++mi) {
        int row0 = bm + warp_m * 64 + mi * 16 + gr;
#pragma unroll
        for (int ni = 0; ni < 4; ++ni) {
            int col = bn + warp_n * 32 + ni * 8 + gc;
            float b0 = cb[col], b1 = cb[col + 1];
            float2 v0, v1;
            v0.x = g_theme[(size_t)row0 * HDIM + col] * (acc[mi][ni][0] * CWINV + b0);
            v0.y = g_theme[(size_t)row0 * HDIM + col + 1] * (acc[mi][ni][1] * CWINV + b1);
            v1.x = g_theme[(size_t)(row0 + 8) * HDIM + col] * (acc[mi][ni][2] * CWINV + b0);
            v1.y = g_theme[(size_t)(row0 + 8) * HDIM + col + 1] * (acc[mi][ni][3] * CWINV + b1);
            *(float2*)&out[(size_t)row0 * HDIM + col] = v0;
            *(float2*)&out[(size_t)(row0 + 8) * HDIM + col] = v1;
        }
    }
}

// ---------------- per-step gating (writes h in swizzled global blocks) ----------
__global__ void gate_kernel(int t, float* __restrict__ dist_out) {
    int b = blockIdx.x;
    int tid = threadIdx.x;
    __shared__ float sfm[LDIM], sim[LDIM];
    const float* xo = g_xo + (size_t)b * NPAD;

    if (tid == 0) {
        float z[LDIM], m = -1e30f;
#pragma unroll
        for (int l = 0; l < LDIM; l++) { z[l] = xo[l]; m = fmaxf(m, z[l]); }
        float s = 0.0f;
#pragma unroll
        for (int l = 0; l < LDIM; l++) { z[l] = __expf(z[l] - m); s += z[l]; }
        float inv = 1.0f / s, cs = 0.0f, dsum = 0.0f;
#pragma unroll
        for (int l = 0; l < LDIM; l++) { cs += z[l] * inv; sfm[l] = cs; dsum += cs; }
        dist_out[b] = 1.0f - dsum * (1.0f / LDIM);
    }
    if (tid == 32) {
        float z[LDIM], m = -1e30f;
#pragma unroll
        for (int l = 0; l < LDIM; l++) { z[l] = xo[LDIM + l]; m = fmaxf(m, z[l]); }
        float s = 0.0f;
#pragma unroll
        for (int l = 0; l < LDIM; l++) { z[l] = __expf(z[l] - m); s += z[l]; }
        float inv = 1.0f / s, cs = 0.0f;
#pragma unroll
        for (int l = LDIM - 1; l >= 0; l--) { cs += z[l] * inv; sim[l] = cs; }
    }
    __syncthreads();

    __half* hslot = g_hring + (size_t)(t % KWIN) * BDIM * HDIM;
    int base = b * HDIM;
    int bmt = b >> 8, r = b & 255;
    for (int idx = tid; idx < HDIM; idx += blockDim.x) {
        int l = idx >> 6;
        float f  = fsig(xo[16 + idx]);
        float ii = fsig(xo[16 + 512 + idx]);
        float oo = fsig(xo[16 + 1024 + idx]);
        float ci = ftanh(xo[16 + 1536 + idx]);
        float cl = g_c[base + idx];
        float fm = sfm[l], im = sim[l], ov = fm * im;
        float cn = ov * (f * cl + ii * ci) + (fm - ov) * cl + (im - ov) * ci;
        float hn = oo * ftanh(cn);
        g_c[base + idx] = cn;
        __half hh = __float2half_rn(hn);
        hslot[base + idx] = hh;
        // swizzled h write for next step's bulk-copied A tiles
        int ch = idx >> 7, s = (idx >> 3) & 15, e = idx & 7;
        g_hsw[(size_t)(bmt * 4 + ch) * ABLK_H + r * 128 + ((s ^ (r & 7)) << 3) + e] = hh;
    }
}

// ---------------- tail kernels ---------------------------------------------------
__global__ void ldis_kernel(const float* __restrict__ dist) {
    int b = blockIdx.x * blockDim.x + threadIdx.x;
    if (b >= BDIM) return;
    float v[KWIN], s = 0.0f;
#pragma unroll
    for (int k = 0; k < KWIN; k++) { s += dist[(size_t)(TDIM - KWIN + k) * BDIM + b]; v[k] = s; }
    float m = -1e30f;
#pragma unroll
    for (int k = 0; k < KWIN; k++) m = fmaxf(m, v[k]);
    float es = 0.0f;
#pragma unroll
    for (int k = 0; k < KWIN; k++) { v[k] = expf(v[k] - m); es += v[k]; }
    float inv = 1.0f / es;
#pragma unroll
    for (int k = 0; k < KWIN; k++) g_ldis[b * KWIN + k] = v[k] * inv;
}

__global__ void meanlh_kernel() {
    int id = blockIdx.x * blockDim.x + threadIdx.x;
    if (id >= BDIM * HDIM) return;
    int b = id >> 9;
    int hh = id & 511;
    float acc = 0.0f;
    size_t lbase = (size_t)b * CONVK + hh * KWIN;
#pragma unroll
    for (int k = 0; k < KWIN; k++) {
        int slot = (TDIM - KWIN + k) % KWIN;
        float hv = __half2float(g_hring[(size_t)slot * BDIM * HDIM + id]);
        float lv = hv * g_ldis[b * KWIN + k];
        g_lh[lbase + k] = __float2half_rn(lv);
        acc += lv;
    }
    g_mh[id] = acc * (1.0f / KWIN);
}

template <int EPI>
__global__ void __launch_bounds__(256) sgemm_kernel(
    const float* __restrict__ A, const float* __restrict__ W,
    const float* __restrict__ bias, float* __restrict__ out, int M, int N, int K)
{
    __shared__ float As[8][128];
    __shared__ float Bs[8][128];
    int tid = threadIdx.x;
    int bm = blockIdx.y * 128;
    int bn = blockIdx.x * 128;
    int ty = tid >> 4, tx = tid & 15;

    float acc[8][8];
#pragma unroll
    for (int i = 0; i < 8; i++)
#pragma unroll
        for (int j = 0; j < 8; j++) acc[i][j] = 0.0f;

    int aRow = tid >> 1, aK = (tid & 1) * 4;
    int bRow = tid >> 5, bCol = (tid & 31) * 4;

    for (int k0 = 0; k0 < K; k0 += 8) {
        int gm = bm + aRow;
#pragma unroll
        for (int j = 0; j < 4; j++) {
            int gk = k0 + aK + j;
            As[aK + j][aRow] = (gm < M && gk < K) ? A[(size_t)gm * K + gk] : 0.0f;
        }
        {
            int gk = k0 + bRow;
#pragma unroll
            for (int j = 0; j < 4; j++) {
                int gn = bn + bCol + j;
                Bs[bRow][bCol + j] = (gk < K && gn < N) ? W[(size_t)gk * N + gn] : 0.0f;
            }
        }
        __syncthreads();
#pragma unroll
        for (int kk = 0; kk < 8; kk++) {
            float a[8], bb[8];
#pragma unroll
            for (int i = 0; i < 8; i++) a[i] = As[kk][ty * 8 + i];
#pragma unroll
            for (int i = 0; i < 8; i++) bb[i] = Bs[kk][tx * 8 + i];
#pragma unroll
            for (int i = 0; i < 8; i++)
#pragma unroll
                for (int j = 0; j < 8; j++) acc[i][j] += a[i] * bb[j];
        }
        __syncthreads();
    }
#pragma unroll
    for (int i = 0; i < 8; i++) {
        int gm = bm + ty * 8 + i;
        if (gm >= M) continue;
#pragma unroll
        for (int j = 0; j < 8; j++) {
            int gn = bn + tx * 8 + j;
            if (gn >= N) continue;
            float v = acc[i][j] + bias[gn];
            if (EPI == 1) v = fmaxf(v, 0.0f);
            if (EPI == 2) v = 1.0f / (1.0f + expf(-v));
            out[(size_t)gm * N + gn] = v;
        }
    }
}

// ---------------- host launcher --------------------------------------------------
extern "C" void kernel_launch(void* const* d_in, const int* in_sizes, int n_in,
                              void* d_out, int out_size) {
    const float* x      = (const float*)d_in[0];
    const float* tmv    = (const float*)d_in[1];
    const float* Wk     = (const float*)d_in[2];
    const float* bk     = (const float*)d_in[3];
    const float* Wr     = (const float*)d_in[4];
    const float* br     = (const float*)d_in[5];
    const float* Ws     = (const float*)d_in[6];
    const float* bs     = (const float*)d_in[7];
    const float* Wrs    = (const float*)d_in[8];
    const float* brs    = (const float*)d_in[9];
    const float* conv_w = (const float*)d_in[10];
    const float* conv_b = (const float*)d_in[11];
    float* out = (float*)d_out;
    float* dist_out = out + (size_t)BDIM * HDIM;   // distance region: (T, B)

    float *p_mh, *p_t1, *p_theme;
    cudaGetSymbolAddress((void**)&p_mh, g_mh);
    cudaGetSymbolAddress((void**)&p_t1, g_t1);
    cudaGetSymbolAddress((void**)&p_theme, g_theme);

    cudaFuncSetAttribute(step_mma_kernel, cudaFuncAttributeMaxDynamicSharedMemorySize,
                         SMEM_BYTES);
    cudaFuncSetAttribute(conv_mma_kernel, cudaFuncAttributeMaxDynamicSharedMemorySize,
                         CSMEM_BYTES);

    // prep (largest id space: T*B*F = 33.5M)
    size_t prep_total = (size_t)TDIM * BDIM * FDIM;
    prep_kernel<<<(unsigned)((prep_total + 255) / 256), 256>>>(x, tmv, Wk, bk, Wr, br,
                                                               conv_w);

    // recurrent scan
    dim3 gstep(NPAD / NTILE, BDIM / MTILE);   // (17, 8)
    for (int t = 0; t < TDIM; t++) {
        step_mma_kernel<<<gstep, 256, SMEM_BYTES>>>(t);
        gate_kernel<<<BDIM, 256>>>(t, dist_out + (size_t)t * BDIM);
    }

    // tail
    ldis_kernel<<<(BDIM + 255) / 256, 256>>>(dist_out);
    meanlh_kernel<<<(BDIM * HDIM) / 256, 256>>>();
    sgemm_kernel<1><<<dim3(1, 16), 256>>>(p_mh, Ws, bs, p_t1, BDIM, H6, HDIM);
    sgemm_kernel<2><<<dim3(4, 16), 256>>>(p_t1, Wrs, brs, p_theme, BDIM, HDIM, H6);
    conv_mma_kernel<<<dim3(HDIM / 128, BDIM / 128), 256, CSMEM_BYTES>>>(conv_b, out);
}